// round 13
// baseline (speedup 1.0000x reference)
#include <cuda_runtime.h>
#include <math.h>

#define B_ 16
#define C_ 64
#define H_ 192
#define W_ 192
#define R_ 64

// ---------------- scratch (device globals; no allocation) ----------------
__device__ float g_cp[B_ * C_];            // [B][C]
__device__ float g_hp[B_ * H_];            // [B][H]
__device__ float g_wp[B_ * W_];            // [B][W]
__device__ float g_RS[B_ * C_ * H_];       // per-plane row sums  [B][C][H]
__device__ float g_CS[B_ * C_ * W_];       // per-plane col sums  [B][C][W]
__device__ float g_T [B_ * R_ * C_];       // p[r]*sigmoid(Cw)    [B][R][C]
__device__ float g_Hw[B_ * H_ * R_];       // sigmoid(Hw)         [B][H][R]
__device__ float g_Ww[B_ * R_ * W_];       // sigmoid(Ww)         [B][R][W]

// ---------------- f32x2 helpers (Blackwell packed fp32) -------------------
__device__ __forceinline__ unsigned long long pk2(float x, float y) {
    unsigned long long r;
    asm("mov.b64 %0, {%1, %2};" : "=l"(r) : "f"(x), "f"(y));
    return r;
}
__device__ __forceinline__ void fma2(unsigned long long& d,
                                     unsigned long long a,
                                     unsigned long long b) {
    asm("fma.rn.f32x2 %0, %1, %2, %3;" : "=l"(d) : "l"(a), "l"(b), "l"(d));
}
__device__ __forceinline__ unsigned long long add2(unsigned long long a,
                                                   unsigned long long b) {
    unsigned long long r;
    asm("add.rn.f32x2 %0, %1, %2;" : "=l"(r) : "l"(a), "l"(b));
    return r;
}
__device__ __forceinline__ float2 upk2(unsigned long long v) {
    float2 f;
    asm("mov.b64 {%0, %1}, %2;" : "=f"(f.x), "=f"(f.y) : "l"(v));
    return f;
}
__device__ __forceinline__ unsigned long long shfl64(unsigned long long v, int off) {
    const unsigned lo = __shfl_xor_sync(0xffffffffu, (unsigned)(v & 0xffffffffu), off);
    const unsigned hi = __shfl_xor_sync(0xffffffffu, (unsigned)(v >> 32), off);
    return ((unsigned long long)hi << 32) | lo;
}

__device__ __forceinline__ float sigmoidf_(float x) {
    return 1.0f / (1.0f + expf(-x));
}

// Scalar multi-value butterfly (16 batches over 32 lanes, 17 shfls).
__device__ __forceinline__ void butterfly16(float (&acc)[B_], int lane) {
    #pragma unroll
    for (int off = 16; off >= 2; off >>= 1) {
        const int nv = off >> 1;
        const bool hi = (lane & off) != 0;
        #pragma unroll
        for (int j = 0; j < nv; j++) {
            float send = hi ? acc[j] : acc[j + nv];
            float recv = __shfl_xor_sync(0xffffffffu, send, off);
            acc[j] = (hi ? acc[j + nv] : acc[j]) + recv;
        }
    }
    acc[0] += __shfl_xor_sync(0xffffffffu, acc[0], 1);
}

// Packed butterfly: 8 f32x2 values (batch j in .lo, j+8 in .hi) over 32 lanes.
__device__ __forceinline__ void butterfly8p(unsigned long long (&v)[8], int lane) {
    #pragma unroll
    for (int off = 16; off >= 4; off >>= 1) {
        const int nv = off >> 2;
        const bool hi = (lane & off) != 0;
        #pragma unroll
        for (int j = 0; j < nv; j++) {
            unsigned long long send = hi ? v[j] : v[j + nv];
            unsigned long long recv = shfl64(send, off);
            v[j] = add2(hi ? v[j + nv] : v[j], recv);
        }
    }
    v[0] = add2(v[0], shfl64(v[0], 2));
    v[0] = add2(v[0], shfl64(v[0], 1));
}

// ---------------- kernel 1: per-plane pools ------------------------------
__global__ void __launch_bounds__(192) pool_kernel(const float* __restrict__ X) {
    const int c = blockIdx.x;
    const int b = blockIdx.y;
    const float* plane = X + ((b * C_ + c) * H_) * (long)W_;

    const int tid  = threadIdx.x;
    const int warp = tid >> 5;
    const int lane = tid & 31;

    __shared__ float scs[6][W_];
    __shared__ float swt[6];

    float col0 = 0.f, col1 = 0.f, col2 = 0.f, col3 = 0.f, col4 = 0.f, col5 = 0.f;
    float tot = 0.f;

    const int h0 = warp * 32;
    for (int i = 0; i < 32; i++) {
        const int h = h0 + i;
        const float* row = plane + h * W_;
        float v0 = row[lane +   0];
        float v1 = row[lane +  32];
        float v2 = row[lane +  64];
        float v3 = row[lane +  96];
        float v4 = row[lane + 128];
        float v5 = row[lane + 160];
        col0 += v0; col1 += v1; col2 += v2; col3 += v3; col4 += v4; col5 += v5;
        float rs = ((v0 + v1) + (v2 + v3)) + (v4 + v5);
        #pragma unroll
        for (int off = 16; off >= 1; off >>= 1)
            rs += __shfl_down_sync(0xffffffffu, rs, off);
        if (lane == 0) {
            g_RS[(b * C_ + c) * H_ + h] = rs;
            tot += rs;
        }
    }
    scs[warp][lane +   0] = col0;
    scs[warp][lane +  32] = col1;
    scs[warp][lane +  64] = col2;
    scs[warp][lane +  96] = col3;
    scs[warp][lane + 128] = col4;
    scs[warp][lane + 160] = col5;
    if (lane == 0) swt[warp] = tot;
    __syncthreads();

    float cs = 0.f;
    #pragma unroll
    for (int j = 0; j < 6; j++) cs += scs[j][tid];
    g_CS[(b * C_ + c) * W_ + tid] = cs;

    if (tid == 0) {
        float t = 0.f;
        #pragma unroll
        for (int j = 0; j < 6; j++) t += swt[j];
        g_cp[b * C_ + c] = t * (1.0f / (H_ * (float)W_));
    }
}

// ---------------- kernel 2: reduce RS/CS over c -> hp, wp ----------------
__global__ void hw_pool_kernel() {
    const int i = blockIdx.x * blockDim.x + threadIdx.x;  // 0 .. B*H-1
    if (i >= B_ * H_) return;
    const int b = i / H_;
    const int h = i - b * H_;
    float s1 = 0.f, s2 = 0.f;
    for (int c = 0; c < C_; c++) {
        s1 += g_RS[(b * C_ + c) * H_ + h];
        s2 += g_CS[(b * C_ + c) * W_ + h];
    }
    g_hp[i] = s1 * (1.0f / (C_ * (float)W_));
    g_wp[i] = s2 * (1.0f / (C_ * (float)H_));
}

// ---------------- kernel 3: ALL sigmoid weights ---------------------------
__global__ void __launch_bounds__(256) weights_kernel(
        const float* __restrict__ Wh, const float* __restrict__ bh,
        const float* __restrict__ Wwp, const float* __restrict__ bw,
        const float* __restrict__ Wc, const float* __restrict__ bc,
        const float* __restrict__ p) {
    const int tid  = threadIdx.x;
    const int warp = tid >> 5;
    const int lane = tid & 31;
    const int branch = blockIdx.y;

    __shared__ unsigned long long sp2[8][H_];   // packed pools (b, b+8)
    __shared__ float spc[B_][C_];               // C-branch pools

    if (branch == 2) {
        if (blockIdx.x >= (R_ * C_) / 16) return;
        // ---- C branch: rows of 64, scalar path ----
        for (int i = tid; i < B_ * C_; i += 256)
            spc[i >> 6][i & 63] = g_cp[i];
        __syncthreads();

        const int m0 = blockIdx.x * 16 + warp * 2;   // 0..4094
        const int m1 = m0 + 1;
        const float* w0 = Wc + m0 * C_;
        const float* w1 = Wc + m1 * C_;
        const float a0 = w0[lane], a1 = w0[lane + 32];
        const float b0 = w1[lane], b1 = w1[lane + 32];

        float acc0[B_], acc1[B_];
        #pragma unroll
        for (int b = 0; b < B_; b++) {
            const float p0 = spc[b][lane], p1 = spc[b][lane + 32];
            acc0[b] = fmaf(a1, p1, a0 * p0);
            acc1[b] = fmaf(b1, p1, b0 * p0);
        }
        butterfly16(acc0, lane);
        butterfly16(acc1, lane);

        if ((lane & 1) == 0) {
            const int batch = lane >> 1;
            const int r0 = m0 >> 6, d0 = m0 & 63;
            const int r1 = m1 >> 6, d1 = m1 & 63;
            g_T[(batch * R_ + r0) * C_ + d0] = p[r0] * sigmoidf_(acc0[0] + bc[m0]);
            g_T[(batch * R_ + r1) * C_ + d1] = p[r1] * sigmoidf_(acc1[0] + bc[m1]);
        }
        return;
    }

    // ---- H/W branches: rows of 192, batch-packed path ----
    {
        const float* pool = branch ? g_wp : g_hp;
        for (int i = tid; i < 8 * H_; i += 256) {
            const int j = i / H_;
            const int h = i - j * H_;
            sp2[j][h] = pk2(pool[j * H_ + h], pool[(j + 8) * H_ + h]);
        }
    }
    __syncthreads();

    const int m0 = blockIdx.x * 16 + warp * 2;   // 0..12286
    const int m1 = m0 + 1;
    const float* Wsrc = branch ? Wwp : Wh;
    const float* bsrc = branch ? bw  : bh;
    const float* wrow0 = Wsrc + (long)m0 * H_;
    const float* wrow1 = Wsrc + (long)m1 * H_;

    float wa[6], wb[6];
    #pragma unroll
    for (int k = 0; k < 6; k++) wa[k] = wrow0[lane + 32 * k];
    #pragma unroll
    for (int k = 0; k < 6; k++) wb[k] = wrow1[lane + 32 * k];

    unsigned long long acc0[8], acc1[8];
    #pragma unroll
    for (int j = 0; j < 8; j++) { acc0[j] = 0ull; acc1[j] = 0ull; }

    #pragma unroll
    for (int k = 0; k < 6; k++) {
        const unsigned long long wA = pk2(wa[k], wa[k]);
        const unsigned long long wB = pk2(wb[k], wb[k]);
        const int hidx = lane + 32 * k;
        #pragma unroll
        for (int j = 0; j < 8; j++) {
            const unsigned long long pv = sp2[j][hidx];
            fma2(acc0[j], wA, pv);
            fma2(acc1[j], wB, pv);
        }
    }
    butterfly8p(acc0, lane);
    butterfly8p(acc1, lane);

    if ((lane & 3) == 0) {
        const int j  = lane >> 2;          // batch pair (j, j+8)
        const int r0 = m0 / H_, d0 = m0 - r0 * H_;
        const int r1 = m1 / H_, d1 = m1 - r1 * H_;
        const float bias0 = bsrc[m0];
        const float bias1 = bsrc[m1];
        const float2 q0 = upk2(acc0[0]);
        const float2 q1 = upk2(acc1[0]);
        const float v0a = sigmoidf_(q0.x + bias0);
        const float v0b = sigmoidf_(q0.y + bias0);
        const float v1a = sigmoidf_(q1.x + bias1);
        const float v1b = sigmoidf_(q1.y + bias1);
        if (branch == 0) {
            g_Hw[((j    ) * H_ + d0) * R_ + r0] = v0a;   // [B][H][R]
            g_Hw[((j + 8) * H_ + d0) * R_ + r0] = v0b;
            g_Hw[((j    ) * H_ + d1) * R_ + r1] = v1a;
            g_Hw[((j + 8) * H_ + d1) * R_ + r1] = v1b;
        } else {
            g_Ww[((j    ) * R_ + r0) * W_ + d0] = v0a;   // [B][R][W]
            g_Ww[((j + 8) * R_ + r0) * W_ + d0] = v0b;
            g_Ww[((j    ) * R_ + r1) * W_ + d1] = v1a;
            g_Ww[((j + 8) * R_ + r1) * W_ + d1] = v1b;
        }
    }
}

// ---------------- kernel 4: main fused GEMM + elementwise ----------------
// Block = (h, w-half, b), 256 threads = 8 warps.
// Warp = one 8-c group (warp-uniform M loads -> true smem broadcast);
// lane = w position; 3 w per thread (w = lane, lane+32, lane+64 in the
// 96-wide half). Per r per warp: 2 broadcast LDS.128 (M) + 3 LDS.32 (V,
// 128B/warp each) = ~5 wavefronts feeding 12 FFMA2 x rt2 = 24 fma cycles
// -> fma-bound with 2x L1 margin.
__global__ void __launch_bounds__(256, 3) main_kernel(const float* __restrict__ X,
                                                      float* __restrict__ out) {
    const int h    = blockIdx.x;   // 0..191
    const int half = blockIdx.y;   // 0..1
    const int b    = blockIdx.z;   // 0..15

    const int tid  = threadIdx.x;
    const int warp = tid >> 5;     // c group: c = 8*warp .. 8*warp+7
    const int lane = tid & 31;     // w base lane

    __shared__ __align__(16) float sM[R_ * C_];   // 16 KB  [r][c]
    __shared__ __align__(16) float sV[R_ * 96];   // 24 KB  [r][w']
    __shared__ float sh[R_];

    if (tid < R_) sh[tid] = g_Hw[(b * H_ + h) * R_ + tid];
    __syncthreads();

    // fill M = T * hw   (T layout [B][R][C], coalesced float4)
    {
        const float4* T4  = (const float4*)(g_T + b * (R_ * C_));
        float4*       sM4 = (float4*)sM;
        for (int i = tid; i < (R_ * C_) / 4; i += 256) {
            float4 t = T4[i];
            const float hv = sh[i >> 4];  // r = i / 16
            t.x *= hv; t.y *= hv; t.z *= hv; t.w *= hv;
            sM4[i] = t;
        }
    }
    // fill V half
    {
        float4* sV4 = (float4*)sV;
        for (int i = tid; i < R_ * 24; i += 256) {
            const int r = i / 24;
            const int j = i - r * 24;
            sV4[r * 24 + j] =
                ((const float4*)(g_Ww + (b * R_ + r) * W_ + half * 96))[j];
        }
    }
    __syncthreads();

    const ulonglong2* sM2 = (const ulonglong2*)sM;  // 16 per row of 64 floats

    unsigned long long acc[4][3];  // [c-pair][w slot]
    #pragma unroll
    for (int i = 0; i < 4; i++)
        #pragma unroll
        for (int k = 0; k < 3; k++) acc[i][k] = 0ull;

    #pragma unroll 8
    for (int r = 0; r < R_; r++) {
        // warp-uniform M loads (true broadcast)
        const ulonglong2 m0 = sM2[r * 16 + warp * 2];      // c pairs 0,1
        const ulonglong2 m1 = sM2[r * 16 + warp * 2 + 1];  // c pairs 2,3
        // per-lane V loads: 128B per warp each
        const float v0 = sV[r * 96 + lane];
        const float v1 = sV[r * 96 + lane + 32];
        const float v2 = sV[r * 96 + lane + 64];

        const unsigned long long B0 = pk2(v0, v0);
        const unsigned long long B1 = pk2(v1, v1);
        const unsigned long long B2 = pk2(v2, v2);

        fma2(acc[0][0], m0.x, B0); fma2(acc[0][1], m0.x, B1); fma2(acc[0][2], m0.x, B2);
        fma2(acc[1][0], m0.y, B0); fma2(acc[1][1], m0.y, B1); fma2(acc[1][2], m0.y, B2);
        fma2(acc[2][0], m1.x, B0); fma2(acc[2][1], m1.x, B1); fma2(acc[2][2], m1.x, B2);
        fma2(acc[3][0], m1.y, B0); fma2(acc[3][1], m1.y, B1); fma2(acc[3][2], m1.y, B2);
    }

    // epilogue: c = 8*warp + 2*cp (+1), w = half*96 + lane + 32k
    const int wbase = half * 96 + lane;
    #pragma unroll
    for (int cp = 0; cp < 4; cp++) {
        const int c0 = 8 * warp + 2 * cp;
        const long i0 = ((long)(b * C_ + c0) * H_ + h) * W_ + wbase;
        const long i1 = i0 + (long)H_ * W_;
        #pragma unroll
        for (int k = 0; k < 3; k++) {
            const float2 q = upk2(acc[cp][k]);
            const long o0 = i0 + 32 * k;
            const long o1 = i1 + 32 * k;
            out[o0] = q.x * X[o0];
            out[o1] = q.y * X[o1];
        }
    }
}

// ---------------- launch ---------------------------------------------------
extern "C" void kernel_launch(void* const* d_in, const int* in_sizes, int n_in,
                              void* d_out, int out_size) {
    const float* X   = (const float*)d_in[0];
    const float* p   = (const float*)d_in[1];
    const float* Wc  = (const float*)d_in[2];
    const float* bc  = (const float*)d_in[3];
    const float* Wh  = (const float*)d_in[4];
    const float* bh  = (const float*)d_in[5];
    const float* Wwp = (const float*)d_in[6];
    const float* bw  = (const float*)d_in[7];
    float* out = (float*)d_out;

    pool_kernel<<<dim3(C_, B_), 192>>>(X);                               // 1
    hw_pool_kernel<<<(B_ * H_ + 255) / 256, 256>>>();                    // 2
    weights_kernel<<<dim3((R_ * H_) / 16, 3), 256>>>(Wh, bh, Wwp, bw,    // 3
                                                     Wc, bc, p);
    main_kernel<<<dim3(H_, 2, B_), 256>>>(X, out);                       // 4
}